// round 9
// baseline (speedup 1.0000x reference)
#include <cuda_runtime.h>

#define BDIM 8
#define CDIM 64
#define NDIM 256
#define FDIM 128
#define EPS 1e-5f

// Scratch (allocation-free rule: __device__ globals)
__device__ unsigned char g_mask[BDIM * CDIM * NDIM];
__device__ float  g_S1[BDIM * CDIM];
__device__ float  g_S2[BDIM * CDIM];
__device__ float2 g_wgt[BDIM * CDIM];     // (w0, w1)

__device__ __forceinline__ float warpsum(float v) {
#pragma unroll
    for (int o = 16; o; o >>= 1) v += __shfl_xor_sync(0xffffffffu, v, o);
    return v;
}

__device__ __forceinline__ float dot4(float4 a, float4 b) {
    return a.x * b.x + a.y * b.y + a.z * b.z + a.w * b.w;
}

// ---------------------------------------------------------------------------
// Kernel 1 (R6-proven, 16.4us): one CTA per (b,c), 256 threads (8 warps),
// 4 rows per warp per iteration (4 interleaved butterfly chains), scalarized
// accumulators via linearity, inline epilogue.
// ---------------------------------------------------------------------------
__global__ void __launch_bounds__(256, 4) k1(const float* __restrict__ h,
                                             const float* __restrict__ op,
                                             const float* __restrict__ opS,
                                             const float* __restrict__ opQ) {
    const int bc  = blockIdx.x;
    const int c   = bc & (CDIM - 1);
    const int tid = threadIdx.x;
    const int w   = tid >> 5, lane = tid & 31;

    const float* hbase = h + (size_t)bc * NDIM * FDIM;
    const float4* op4  = (const float4*)(op  + c * 2 * FDIM);
    const float4* opS4 = (const float4*)(opS + c * 2 * FDIM);
    const float4* opQ4 = (const float4*)(opQ + c * 2 * FDIM);
    const float4 ohi  = op4[32 + lane];   // op[c][128:256] (h part)
    const float4 oSlo = opS4[lane];       // opS[c][0:128]  (mean part)
    const float4 oQlo = opQ4[lane];       // opQ[c][0:128]  (mean part)

    // s_lo = dot(source, op_lo) (source row is L1-hot; once per warp)
    const float4 s0 = ((const float4*)hbase)[lane];
    const float s_lo = warpsum(dot4(s0, op4[lane]));

    __shared__ float accs[7];  // [dS_s, dQ_t, dQ_s, sm_t, sm_s, sq_t, sq_s]
    if (tid < 7) accs[tid] = 0.f;
    __syncthreads();

    float a_dSs = 0.f, a_dQt = 0.f, a_dQs = 0.f;
    float a_smt = 0.f, a_sms = 0.f, a_sqt = 0.f, a_sqs = 0.f;

    // Warp w handles rows n0 = it*32 + w*4 .. +3  (8 iterations)
#pragma unroll 2
    for (int it = 0; it < 8; it++) {
        const int n0 = it * 32 + w * 4;
        const float4* r = (const float4*)(hbase + (size_t)n0 * FDIM);
        const float4 v0 = r[lane];
        const float4 v1 = r[32 + lane];
        const float4 v2 = r[64 + lane];
        const float4 v3 = r[96 + lane];

        float p0 = dot4(v0, ohi);
        float p1 = dot4(v1, ohi);
        float p2 = dot4(v2, ohi);
        float p3 = dot4(v3, ohi);
        // 4 interleaved butterfly chains
#pragma unroll
        for (int o = 16; o; o >>= 1) {
            p0 += __shfl_xor_sync(0xffffffffu, p0, o);
            p1 += __shfl_xor_sync(0xffffffffu, p1, o);
            p2 += __shfl_xor_sync(0xffffffffu, p2, o);
            p3 += __shfl_xor_sync(0xffffffffu, p3, o);
        }
        const float m0 = (s_lo + p0) >= 0.f ? 1.f : 0.f;
        const float m1 = (s_lo + p1) >= 0.f ? 1.f : 0.f;
        const float m2 = (s_lo + p2) >= 0.f ? 1.f : 0.f;
        const float m3 = (s_lo + p3) >= 0.f ? 1.f : 0.f;
        if (lane == 0) {
            uchar4 mk;
            mk.x = (unsigned char)m0; mk.y = (unsigned char)m1;
            mk.z = (unsigned char)m2; mk.w = (unsigned char)m3;
            *(uchar4*)(g_mask + bc * NDIM + n0) = mk;
        }

        // Per-row scalar partials; tot-accums have no mask dependency.
        {
            float pS = dot4(v0, oSlo); a_dSs = fmaf(m0, pS, a_dSs);
            float pQ = dot4(v0, oQlo); a_dQt += pQ; a_dQs = fmaf(m0, pQ, a_dQs);
            float ps = v0.x + v0.y + v0.z + v0.w; a_smt += ps; a_sms = fmaf(m0, ps, a_sms);
            float pq = dot4(v0, v0); a_sqt += pq; a_sqs = fmaf(m0, pq, a_sqs);
        }
        {
            float pS = dot4(v1, oSlo); a_dSs = fmaf(m1, pS, a_dSs);
            float pQ = dot4(v1, oQlo); a_dQt += pQ; a_dQs = fmaf(m1, pQ, a_dQs);
            float ps = v1.x + v1.y + v1.z + v1.w; a_smt += ps; a_sms = fmaf(m1, ps, a_sms);
            float pq = dot4(v1, v1); a_sqt += pq; a_sqs = fmaf(m1, pq, a_sqs);
        }
        {
            float pS = dot4(v2, oSlo); a_dSs = fmaf(m2, pS, a_dSs);
            float pQ = dot4(v2, oQlo); a_dQt += pQ; a_dQs = fmaf(m2, pQ, a_dQs);
            float ps = v2.x + v2.y + v2.z + v2.w; a_smt += ps; a_sms = fmaf(m2, ps, a_sms);
            float pq = dot4(v2, v2); a_sqt += pq; a_sqs = fmaf(m2, pq, a_sqs);
        }
        {
            float pS = dot4(v3, oSlo); a_dSs = fmaf(m3, pS, a_dSs);
            float pQ = dot4(v3, oQlo); a_dQt += pQ; a_dQs = fmaf(m3, pQ, a_dQs);
            float ps = v3.x + v3.y + v3.z + v3.w; a_smt += ps; a_sms = fmaf(m3, ps, a_sms);
            float pq = dot4(v3, v3); a_sqt += pq; a_sqs = fmaf(m3, pq, a_sqs);
        }
    }

    // Fold the 7 per-lane accumulators (interleaved butterflies), then smem.
#pragma unroll
    for (int o = 16; o; o >>= 1) {
        a_dSs += __shfl_xor_sync(0xffffffffu, a_dSs, o);
        a_dQt += __shfl_xor_sync(0xffffffffu, a_dQt, o);
        a_dQs += __shfl_xor_sync(0xffffffffu, a_dQs, o);
        a_smt += __shfl_xor_sync(0xffffffffu, a_smt, o);
        a_sms += __shfl_xor_sync(0xffffffffu, a_sms, o);
        a_sqt += __shfl_xor_sync(0xffffffffu, a_sqt, o);
        a_sqs += __shfl_xor_sync(0xffffffffu, a_sqs, o);
    }
    if (lane == 0) {
        atomicAdd(&accs[0], a_dSs);
        atomicAdd(&accs[1], a_dQt);
        atomicAdd(&accs[2], a_dQs);
        atomicAdd(&accs[3], a_smt);
        atomicAdd(&accs[4], a_sms);
        atomicAdd(&accs[5], a_sqt);
        atomicAdd(&accs[6], a_sqs);
    }
    __syncthreads();

    // Epilogue (warp 0): source dots with opS_hi/opQ_hi, softmax, BN partials
    if (tid < 32) {
        const float4 oShi = opS4[32 + lane];
        const float4 oQhi = opQ4[32 + lane];
        float tSrcS = dot4(s0, oShi);
        float tSrcQ = dot4(s0, oQhi);
#pragma unroll
        for (int o = 16; o; o >>= 1) {
            tSrcS += __shfl_xor_sync(0xffffffffu, tSrcS, o);
            tSrcQ += __shfl_xor_sync(0xffffffffu, tSrcQ, o);
        }
        if (lane == 0) {
            const float tS = accs[0] * (1.f / NDIM) + tSrcS;
            const float tQ = (accs[1] - accs[2]) * (1.f / NDIM) + tSrcQ;
            const float mx = fmaxf(tS, tQ);
            const float e0 = expf(tS - mx), e1 = expf(tQ - mx);
            const float inv = 1.f / (e0 + e1);
            const float w0 = e0 * inv, w1 = e1 * inv;
            g_wgt[bc] = make_float2(w0, w1);
            g_S1[bc] = w0 * accs[4] + w1 * (accs[3] - accs[4]);
            g_S2[bc] = w0 * w0 * accs[6] + w1 * w1 * (accs[5] - accs[6]);
        }
    }
}

// ---------------------------------------------------------------------------
// Kernel 3: streaming elementwise with self-computed BN stats.
// Block = 512 float4 = 2048 elements, fully inside one (b,c) (16 blocks/bc).
// Prologue (threads 0-7): fold batch partials for this channel -> mean/rstd
// -> (scale0, scale1, shift) in smem. Main: 2 float4 per thread.
// ---------------------------------------------------------------------------
__global__ __launch_bounds__(256) void k3(const float* __restrict__ h,
                                          const float* __restrict__ gamma,
                                          const float* __restrict__ beta,
                                          float* __restrict__ out) {
    const int tid = threadIdx.x;
    const int bc  = blockIdx.x >> 4;          // 16 blocks per (b,c)
    const int c   = bc & (CDIM - 1);

    __shared__ float sh[3];  // scale0 (supp), scale1 (query), shift
    if (tid < 8) {
        float s1 = g_S1[tid * CDIM + c];
        float s2 = g_S2[tid * CDIM + c];
#pragma unroll
        for (int o = 4; o; o >>= 1) {
            s1 += __shfl_xor_sync(0xffu, s1, o);
            s2 += __shfl_xor_sync(0xffu, s2, o);
        }
        if (tid == 0) {
            const float inv = 1.f / (float)(BDIM * NDIM * FDIM);
            const float mean = s1 * inv;
            const float var = s2 * inv - mean * mean;
            const float rstd = rsqrtf(var + EPS);
            const float gr = gamma[c] * rstd;
            const float2 wv = g_wgt[bc];
            sh[0] = wv.x * gr;
            sh[1] = wv.y * gr;
            sh[2] = beta[c] - mean * gr;
        }
    }
    __syncthreads();
    const float sc0 = sh[0], sc1 = sh[1], shift = sh[2];

    const int i0 = blockIdx.x * 512 + tid;    // first float4
#pragma unroll
    for (int u = 0; u < 2; u++) {
        const int i = i0 + u * 256;
        const unsigned char m = g_mask[i >> 5];   // uniform per warp (one row per warp)
        const float scale = m ? sc0 : sc1;
        const float4 hv = ((const float4*)h)[i];
        float4 y;
        y.x = hv.x * scale + shift;
        y.y = hv.y * scale + shift;
        y.z = hv.z * scale + shift;
        y.w = hv.w * scale + shift;
        y.x = (y.x > 0.f) ? y.x : (__expf(y.x) - 1.f);
        y.y = (y.y > 0.f) ? y.y : (__expf(y.y) - 1.f);
        y.z = (y.z > 0.f) ? y.z : (__expf(y.z) - 1.f);
        y.w = (y.w > 0.f) ? y.w : (__expf(y.w) - 1.f);
        ((float4*)out)[i] = y;
    }
}

extern "C" void kernel_launch(void* const* d_in, const int* in_sizes, int n_in,
                              void* d_out, int out_size) {
    const float* h     = (const float*)d_in[0];
    const float* op    = (const float*)d_in[1];
    const float* opS   = (const float*)d_in[2];
    const float* opQ   = (const float*)d_in[3];
    const float* gamma = (const float*)d_in[4];
    const float* beta  = (const float*)d_in[5];
    float* out = (float*)d_out;

    k1<<<BDIM * CDIM, 256>>>(h, op, opS, opQ);
    const int total4 = (BDIM * CDIM * NDIM * FDIM) / 4;  // 4,194,304
    k3<<<total4 / 512, 256>>>(h, gamma, beta, out);
}

// round 10
// speedup vs baseline: 1.2111x; 1.2111x over previous
#include <cuda_runtime.h>

#define BDIM 8
#define CDIM 64
#define NDIM 256
#define FDIM 128
#define EPS 1e-5f

// Scratch (allocation-free rule: __device__ globals)
__device__ unsigned char g_mask[BDIM * CDIM * NDIM];
__device__ float  g_S1[BDIM * CDIM];
__device__ float  g_S2[BDIM * CDIM];
__device__ float2 g_wgt[BDIM * CDIM];     // (w0, w1)
__device__ float2 g_scale[BDIM * CDIM];   // (w0*gr, w1*gr)
__device__ float  g_shift[BDIM * CDIM];   // beta - mean*gr

__device__ __forceinline__ float warpsum(float v) {
#pragma unroll
    for (int o = 16; o; o >>= 1) v += __shfl_xor_sync(0xffffffffu, v, o);
    return v;
}

__device__ __forceinline__ float dot4(float4 a, float4 b) {
    return a.x * b.x + a.y * b.y + a.z * b.z + a.w * b.w;
}

// ---------------------------------------------------------------------------
// Kernel 1 (R6-proven, 16.4us): one CTA per (b,c), 256 threads (8 warps),
// 4 rows per warp per iteration (4 interleaved butterfly chains), scalarized
// accumulators via linearity, inline epilogue.
// ---------------------------------------------------------------------------
__global__ void __launch_bounds__(256, 4) k1(const float* __restrict__ h,
                                             const float* __restrict__ op,
                                             const float* __restrict__ opS,
                                             const float* __restrict__ opQ) {
    const int bc  = blockIdx.x;
    const int c   = bc & (CDIM - 1);
    const int tid = threadIdx.x;
    const int w   = tid >> 5, lane = tid & 31;

    const float* hbase = h + (size_t)bc * NDIM * FDIM;
    const float4* op4  = (const float4*)(op  + c * 2 * FDIM);
    const float4* opS4 = (const float4*)(opS + c * 2 * FDIM);
    const float4* opQ4 = (const float4*)(opQ + c * 2 * FDIM);
    const float4 ohi  = op4[32 + lane];   // op[c][128:256] (h part)
    const float4 oSlo = opS4[lane];       // opS[c][0:128]  (mean part)
    const float4 oQlo = opQ4[lane];       // opQ[c][0:128]  (mean part)

    // s_lo = dot(source, op_lo) (source row is L1-hot; once per warp)
    const float4 s0 = ((const float4*)hbase)[lane];
    const float s_lo = warpsum(dot4(s0, op4[lane]));

    __shared__ float accs[7];  // [dS_s, dQ_t, dQ_s, sm_t, sm_s, sq_t, sq_s]
    if (tid < 7) accs[tid] = 0.f;
    __syncthreads();

    float a_dSs = 0.f, a_dQt = 0.f, a_dQs = 0.f;
    float a_smt = 0.f, a_sms = 0.f, a_sqt = 0.f, a_sqs = 0.f;

    // Warp w handles rows n0 = it*32 + w*4 .. +3  (8 iterations)
#pragma unroll 2
    for (int it = 0; it < 8; it++) {
        const int n0 = it * 32 + w * 4;
        const float4* r = (const float4*)(hbase + (size_t)n0 * FDIM);
        const float4 v0 = r[lane];
        const float4 v1 = r[32 + lane];
        const float4 v2 = r[64 + lane];
        const float4 v3 = r[96 + lane];

        float p0 = dot4(v0, ohi);
        float p1 = dot4(v1, ohi);
        float p2 = dot4(v2, ohi);
        float p3 = dot4(v3, ohi);
        // 4 interleaved butterfly chains
#pragma unroll
        for (int o = 16; o; o >>= 1) {
            p0 += __shfl_xor_sync(0xffffffffu, p0, o);
            p1 += __shfl_xor_sync(0xffffffffu, p1, o);
            p2 += __shfl_xor_sync(0xffffffffu, p2, o);
            p3 += __shfl_xor_sync(0xffffffffu, p3, o);
        }
        const float m0 = (s_lo + p0) >= 0.f ? 1.f : 0.f;
        const float m1 = (s_lo + p1) >= 0.f ? 1.f : 0.f;
        const float m2 = (s_lo + p2) >= 0.f ? 1.f : 0.f;
        const float m3 = (s_lo + p3) >= 0.f ? 1.f : 0.f;
        if (lane == 0) {
            uchar4 mk;
            mk.x = (unsigned char)m0; mk.y = (unsigned char)m1;
            mk.z = (unsigned char)m2; mk.w = (unsigned char)m3;
            *(uchar4*)(g_mask + bc * NDIM + n0) = mk;
        }

        // Per-row scalar partials; tot-accums have no mask dependency.
        {
            float pS = dot4(v0, oSlo); a_dSs = fmaf(m0, pS, a_dSs);
            float pQ = dot4(v0, oQlo); a_dQt += pQ; a_dQs = fmaf(m0, pQ, a_dQs);
            float ps = v0.x + v0.y + v0.z + v0.w; a_smt += ps; a_sms = fmaf(m0, ps, a_sms);
            float pq = dot4(v0, v0); a_sqt += pq; a_sqs = fmaf(m0, pq, a_sqs);
        }
        {
            float pS = dot4(v1, oSlo); a_dSs = fmaf(m1, pS, a_dSs);
            float pQ = dot4(v1, oQlo); a_dQt += pQ; a_dQs = fmaf(m1, pQ, a_dQs);
            float ps = v1.x + v1.y + v1.z + v1.w; a_smt += ps; a_sms = fmaf(m1, ps, a_sms);
            float pq = dot4(v1, v1); a_sqt += pq; a_sqs = fmaf(m1, pq, a_sqs);
        }
        {
            float pS = dot4(v2, oSlo); a_dSs = fmaf(m2, pS, a_dSs);
            float pQ = dot4(v2, oQlo); a_dQt += pQ; a_dQs = fmaf(m2, pQ, a_dQs);
            float ps = v2.x + v2.y + v2.z + v2.w; a_smt += ps; a_sms = fmaf(m2, ps, a_sms);
            float pq = dot4(v2, v2); a_sqt += pq; a_sqs = fmaf(m2, pq, a_sqs);
        }
        {
            float pS = dot4(v3, oSlo); a_dSs = fmaf(m3, pS, a_dSs);
            float pQ = dot4(v3, oQlo); a_dQt += pQ; a_dQs = fmaf(m3, pQ, a_dQs);
            float ps = v3.x + v3.y + v3.z + v3.w; a_smt += ps; a_sms = fmaf(m3, ps, a_sms);
            float pq = dot4(v3, v3); a_sqt += pq; a_sqs = fmaf(m3, pq, a_sqs);
        }
    }

    // Fold the 7 per-lane accumulators (interleaved butterflies), then smem.
#pragma unroll
    for (int o = 16; o; o >>= 1) {
        a_dSs += __shfl_xor_sync(0xffffffffu, a_dSs, o);
        a_dQt += __shfl_xor_sync(0xffffffffu, a_dQt, o);
        a_dQs += __shfl_xor_sync(0xffffffffu, a_dQs, o);
        a_smt += __shfl_xor_sync(0xffffffffu, a_smt, o);
        a_sms += __shfl_xor_sync(0xffffffffu, a_sms, o);
        a_sqt += __shfl_xor_sync(0xffffffffu, a_sqt, o);
        a_sqs += __shfl_xor_sync(0xffffffffu, a_sqs, o);
    }
    if (lane == 0) {
        atomicAdd(&accs[0], a_dSs);
        atomicAdd(&accs[1], a_dQt);
        atomicAdd(&accs[2], a_dQs);
        atomicAdd(&accs[3], a_smt);
        atomicAdd(&accs[4], a_sms);
        atomicAdd(&accs[5], a_sqt);
        atomicAdd(&accs[6], a_sqs);
    }
    __syncthreads();

    // Epilogue (warp 0): source dots with opS_hi/opQ_hi, softmax, BN partials
    if (tid < 32) {
        const float4 oShi = opS4[32 + lane];
        const float4 oQhi = opQ4[32 + lane];
        float tSrcS = dot4(s0, oShi);
        float tSrcQ = dot4(s0, oQhi);
#pragma unroll
        for (int o = 16; o; o >>= 1) {
            tSrcS += __shfl_xor_sync(0xffffffffu, tSrcS, o);
            tSrcQ += __shfl_xor_sync(0xffffffffu, tSrcQ, o);
        }
        if (lane == 0) {
            const float tS = accs[0] * (1.f / NDIM) + tSrcS;
            const float tQ = (accs[1] - accs[2]) * (1.f / NDIM) + tSrcQ;
            const float mx = fmaxf(tS, tQ);
            const float e0 = expf(tS - mx), e1 = expf(tQ - mx);
            const float inv = 1.f / (e0 + e1);
            const float w0 = e0 * inv, w1 = e1 * inv;
            g_wgt[bc] = make_float2(w0, w1);
            g_S1[bc] = w0 * accs[4] + w1 * (accs[3] - accs[4]);
            g_S2[bc] = w0 * w0 * accs[6] + w1 * w1 * (accs[5] - accs[6]);
        }
    }
}

// ---------------------------------------------------------------------------
// Kernel 2: per-channel stats, then per-(b,c) scale/shift. One 512-thr block.
// ---------------------------------------------------------------------------
__global__ __launch_bounds__(512) void k2(const float* __restrict__ gamma,
                                          const float* __restrict__ beta) {
    __shared__ float2 s_stat[CDIM];
    const int t = threadIdx.x;
    if (t < CDIM) {
        float s1 = 0.f, s2 = 0.f;
#pragma unroll
        for (int b = 0; b < BDIM; b++) {
            s1 += g_S1[b * CDIM + t];
            s2 += g_S2[b * CDIM + t];
        }
        const float inv = 1.f / (float)(BDIM * NDIM * FDIM);
        const float mean = s1 * inv;
        const float var = s2 * inv - mean * mean;
        s_stat[t] = make_float2(mean, rsqrtf(var + EPS));
    }
    __syncthreads();
    const int bc = t;  // 512 = BDIM*CDIM
    const int c = bc & (CDIM - 1);
    const float2 st = s_stat[c];
    const float gr = gamma[c] * st.y;
    const float2 wv = g_wgt[bc];
    g_scale[bc] = make_float2(wv.x * gr, wv.y * gr);
    g_shift[bc] = beta[c] - st.x * gr;
}

// ---------------------------------------------------------------------------
// Kernel 3: streaming elementwise: elu(h*scale + shift), 2 float4 per thread.
// No prologue, no syncthreads: per-bc constants precomputed by k2.
// ---------------------------------------------------------------------------
__global__ __launch_bounds__(256) void k3(const float* __restrict__ h,
                                          float* __restrict__ out) {
    const int tid = threadIdx.x;
    const int i0  = blockIdx.x * 512 + tid;   // first float4 index
    const int bc  = i0 >> 13;                 // 8192 float4 per (b,c); block spans one bc
    const float2 sc = g_scale[bc];
    const float shift = g_shift[bc];

#pragma unroll
    for (int u = 0; u < 2; u++) {
        const int i = i0 + u * 256;
        const unsigned char m = g_mask[i >> 5];   // uniform per warp (one row per warp)
        const float scale = m ? sc.x : sc.y;
        const float4 hv = ((const float4*)h)[i];
        float4 y;
        y.x = hv.x * scale + shift;
        y.y = hv.y * scale + shift;
        y.z = hv.z * scale + shift;
        y.w = hv.w * scale + shift;
        y.x = (y.x > 0.f) ? y.x : (__expf(y.x) - 1.f);
        y.y = (y.y > 0.f) ? y.y : (__expf(y.y) - 1.f);
        y.z = (y.z > 0.f) ? y.z : (__expf(y.z) - 1.f);
        y.w = (y.w > 0.f) ? y.w : (__expf(y.w) - 1.f);
        ((float4*)out)[i] = y;
    }
}

extern "C" void kernel_launch(void* const* d_in, const int* in_sizes, int n_in,
                              void* d_out, int out_size) {
    const float* h     = (const float*)d_in[0];
    const float* op    = (const float*)d_in[1];
    const float* opS   = (const float*)d_in[2];
    const float* opQ   = (const float*)d_in[3];
    const float* gamma = (const float*)d_in[4];
    const float* beta  = (const float*)d_in[5];
    float* out = (float*)d_out;

    k1<<<BDIM * CDIM, 256>>>(h, op, opS, opQ);
    k2<<<1, 512>>>(gamma, beta);
    const int total4 = (BDIM * CDIM * NDIM * FDIM) / 4;  // 4,194,304
    k3<<<total4 / 512, 256>>>(h, out);
}